// round 1
// baseline (speedup 1.0000x reference)
#include <cuda_runtime.h>
#include <cuda_bf16.h>
#include <cfloat>
#include <cstdint>

// Problem constants
#define BQ   2048      // queries
#define NB   50000     // codebook entries
#define NBP  50048     // padded to 391*128
#define DIM  128
#define TOPK 20

// ---------------- device scratch (static globals: no allocation allowed) ---
__device__ float g_q[2][BQ * DIM];          // staged queries: [0]=renormed z_rot, [1]=2*z_trans
__device__ float g_zq[BQ];                  // ||z_trans||^2
__device__ float g_bq[NBP];                 // ||z_trans_book||^2 (zero-init beyond NB)
__device__ float g_scores[(size_t)2 * BQ * NBP];   // ~820 MB score scratch

// ---------------- prep: renorm z_rot, scale z_trans, ||z||^2 ---------------
__global__ void prep_queries(const float* __restrict__ z_rot,
                             const float* __restrict__ z_trans) {
    int warp = (blockIdx.x * blockDim.x + threadIdx.x) >> 5;
    int lane = threadIdx.x & 31;
    if (warp >= BQ) return;

    // z_rot row: renorm
    float4 v = reinterpret_cast<const float4*>(z_rot + (size_t)warp * DIM)[lane];
    float s = v.x * v.x + v.y * v.y + v.z * v.z + v.w * v.w;
    #pragma unroll
    for (int o = 16; o; o >>= 1) s += __shfl_xor_sync(0xFFFFFFFFu, s, o);
    float inv = 1.0f / sqrtf(s);
    float4 w = make_float4(v.x * inv, v.y * inv, v.z * inv, v.w * inv);
    reinterpret_cast<float4*>(g_q[0] + (size_t)warp * DIM)[lane] = w;

    // z_trans row: 2*z and ||z||^2
    float4 t = reinterpret_cast<const float4*>(z_trans + (size_t)warp * DIM)[lane];
    float sq = t.x * t.x + t.y * t.y + t.z * t.z + t.w * t.w;
    #pragma unroll
    for (int o = 16; o; o >>= 1) sq += __shfl_xor_sync(0xFFFFFFFFu, sq, o);
    float4 t2 = make_float4(2.0f * t.x, 2.0f * t.y, 2.0f * t.z, 2.0f * t.w);
    reinterpret_cast<float4*>(g_q[1] + (size_t)warp * DIM)[lane] = t2;
    if (lane == 0) g_zq[warp] = sq;
}

// ---------------- prep: ||book||^2 per row ---------------------------------
__global__ void prep_bq(const float* __restrict__ z_trans_book) {
    int warp = (blockIdx.x * blockDim.x + threadIdx.x) >> 5;
    int lane = threadIdx.x & 31;
    if (warp >= NB) return;
    float4 v = reinterpret_cast<const float4*>(z_trans_book + (size_t)warp * DIM)[lane];
    float s = v.x * v.x + v.y * v.y + v.z * v.z + v.w * v.w;
    #pragma unroll
    for (int o = 16; o; o >>= 1) s += __shfl_xor_sync(0xFFFFFFFFu, s, o);
    if (lane == 0) g_bq[warp] = s;
}

// ---------------- GEMM: scores[p][q][n] -------------------------------------
// Tile: 128 queries x 128 books, K=128 fully resident. 256 threads, 8x8/thread.
#define TPAD 132   // padded row stride in floats (16B aligned, reduces conflicts)

__global__ void __launch_bounds__(256, 1)
score_gemm(const float* __restrict__ z_rot_book,
           const float* __restrict__ z_trans_book) {
    extern __shared__ float smem[];
    float* Qs = smem;                 // [128][TPAD]
    float* Bs = smem + 128 * TPAD;    // [128][TPAD]

    const int p     = blockIdx.z;
    const int qbase = blockIdx.y * 128;
    const int nbase = blockIdx.x * 128;
    const int tid   = threadIdx.x;
    const int tx    = tid & 15;       // book lane group
    const int ty    = tid >> 4;       // query lane group

    const float* Qg = g_q[p];
    const float* Bg = (p == 0) ? z_rot_book : z_trans_book;

    // Load Q tile (128x128 floats) — warp covers one 512B row per iteration
    #pragma unroll
    for (int it = 0; it < 16; it++) {
        int f   = tid + it * 256;
        int row = f >> 5;
        int c4  = f & 31;
        float4 v = reinterpret_cast<const float4*>(Qg + (size_t)(qbase + row) * DIM)[c4];
        *reinterpret_cast<float4*>(&Qs[row * TPAD + c4 * 4]) = v;
    }
    // Load B tile (guard rows beyond NB with zeros)
    #pragma unroll
    for (int it = 0; it < 16; it++) {
        int f   = tid + it * 256;
        int row = f >> 5;
        int c4  = f & 31;
        int gn  = nbase + row;
        float4 v = make_float4(0.f, 0.f, 0.f, 0.f);
        if (gn < NB)
            v = reinterpret_cast<const float4*>(Bg + (size_t)gn * DIM)[c4];
        *reinterpret_cast<float4*>(&Bs[row * TPAD + c4 * 4]) = v;
    }
    __syncthreads();

    float acc[8][8];
    #pragma unroll
    for (int i = 0; i < 8; i++)
        #pragma unroll
        for (int j = 0; j < 8; j++) acc[i][j] = 0.0f;

    #pragma unroll 4
    for (int k4 = 0; k4 < 32; k4++) {
        float4 qv[8];
        #pragma unroll
        for (int i = 0; i < 8; i++)
            qv[i] = *reinterpret_cast<const float4*>(&Qs[(ty + 16 * i) * TPAD + k4 * 4]);
        #pragma unroll
        for (int j = 0; j < 8; j++) {
            float4 bv = *reinterpret_cast<const float4*>(&Bs[(tx + 16 * j) * TPAD + k4 * 4]);
            #pragma unroll
            for (int i = 0; i < 8; i++) {
                acc[i][j] += qv[i].x * bv.x;
                acc[i][j] += qv[i].y * bv.y;
                acc[i][j] += qv[i].z * bv.z;
                acc[i][j] += qv[i].w * bv.w;
            }
        }
    }

    // Epilogue: euclid fixups (acc already holds 2*z.b since Q staged as 2z)
    float zqv[8], bqv[8];
    if (p == 1) {
        #pragma unroll
        for (int i = 0; i < 8; i++) zqv[i] = g_zq[qbase + ty + 16 * i];
        #pragma unroll
        for (int j = 0; j < 8; j++) bqv[j] = g_bq[nbase + tx + 16 * j];
    } else {
        #pragma unroll
        for (int i = 0; i < 8; i++) zqv[i] = 0.0f;
        #pragma unroll
        for (int j = 0; j < 8; j++) bqv[j] = 0.0f;
    }

    float* Sg = g_scores + ((size_t)p * BQ + qbase) * NBP + nbase;
    #pragma unroll
    for (int i = 0; i < 8; i++) {
        int q = ty + 16 * i;
        #pragma unroll
        for (int j = 0; j < 8; j++) {
            int n = tx + 16 * j;
            Sg[(size_t)q * NBP + n] = acc[i][j] - zqv[i] - bqv[j];
        }
    }
}

// ---------------- top-k + gather ----------------
__global__ void __launch_bounds__(256)
topk_kernel(const float* __restrict__ rot_book,
            const float* __restrict__ trans_book,
            float* __restrict__ out) {
    const int p   = blockIdx.x >> 11;      // 0..1
    const int r   = blockIdx.x & 2047;     // 0..2047
    const int tid = threadIdx.x;
    const float* s = g_scores + ((size_t)p * BQ + r) * NBP;

    // per-thread top-20 (registers, predicated writes)
    float lv[TOPK];
    int   li[TOPK];
    #pragma unroll
    for (int t = 0; t < TOPK; t++) { lv[t] = -FLT_MAX; li[t] = 0x7FFFFFFF; }
    float vmin = -FLT_MAX; int minidx = 0x7FFFFFFF; int minslot = 0;

    for (int n = tid; n < NB; n += 256) {
        float v = s[n];
        if (v > vmin || (v == vmin && n < minidx)) {
            #pragma unroll
            for (int t = 0; t < TOPK; t++)
                if (t == minslot) { lv[t] = v; li[t] = n; }
            vmin = lv[0]; minidx = li[0]; minslot = 0;
            #pragma unroll
            for (int t = 1; t < TOPK; t++)
                if (lv[t] < vmin || (lv[t] == vmin && li[t] > minidx)) {
                    vmin = lv[t]; minidx = li[t]; minslot = t;
                }
        }
    }

    __shared__ float sv[256 * TOPK];
    __shared__ int   si[256 * TOPK];
    __shared__ float wv[8];
    __shared__ int   wi[8], wp[8];

    #pragma unroll
    for (int t = 0; t < TOPK; t++) {
        sv[tid * TOPK + t] = lv[t];
        si[tid * TOPK + t] = li[t];
    }
    __syncthreads();

    const size_t BK = (size_t)BQ * TOPK;

    for (int k = 0; k < TOPK; k++) {
        // local best over strided slice of the 5120 candidates
        float bv = -FLT_MAX; int bi = 0x7FFFFFFF; int bp = 0;
        #pragma unroll
        for (int e = 0; e < TOPK; e++) {
            int pos = tid + e * 256;
            float v = sv[pos]; int ii = si[pos];
            if (v > bv || (v == bv && ii < bi)) { bv = v; bi = ii; bp = pos; }
        }
        // warp reduce
        #pragma unroll
        for (int o = 16; o; o >>= 1) {
            float ov = __shfl_down_sync(0xFFFFFFFFu, bv, o);
            int   oi = __shfl_down_sync(0xFFFFFFFFu, bi, o);
            int   op = __shfl_down_sync(0xFFFFFFFFu, bp, o);
            if (ov > bv || (ov == bv && oi < bi)) { bv = ov; bi = oi; bp = op; }
        }
        if ((tid & 31) == 0) { int w = tid >> 5; wv[w] = bv; wi[w] = bi; wp[w] = bp; }
        __syncthreads();
        if (tid == 0) {
            float gv = wv[0]; int gi = wi[0]; int gp = wp[0];
            #pragma unroll
            for (int w = 1; w < 8; w++) {
                if (wv[w] > gv || (wv[w] == gv && wi[w] < gi)) { gv = wv[w]; gi = wi[w]; gp = wp[w]; }
            }
            // remove winner
            sv[gp] = -FLT_MAX; si[gp] = 0x7FFFFFFF;
            size_t rk = (size_t)r * TOPK + k;
            if (p == 0) {
                out[rk]              = gv;               // vals_cos
                out[BK + rk]         = (float)gi;        // ind_cos
                out[2 * BK + rk]     = rot_book[gi];     // labels_rot [B,K,1]
            } else {
                out[3 * BK + rk]     = gv;               // vals_euc
                out[4 * BK + rk]     = (float)gi;        // ind_euc
                out[5 * BK + rk * 3 + 0] = trans_book[(size_t)gi * 3 + 0];
                out[5 * BK + rk * 3 + 1] = trans_book[(size_t)gi * 3 + 1];
                out[5 * BK + rk * 3 + 2] = trans_book[(size_t)gi * 3 + 2];
            }
        }
        __syncthreads();
    }
}

// ---------------- launch ----------------
extern "C" void kernel_launch(void* const* d_in, const int* in_sizes, int n_in,
                              void* d_out, int out_size) {
    const float* z_rot        = (const float*)d_in[0];
    const float* z_trans      = (const float*)d_in[1];
    const float* z_rot_book   = (const float*)d_in[2];
    const float* z_trans_book = (const float*)d_in[3];
    const float* rot_book     = (const float*)d_in[4];
    const float* trans_book   = (const float*)d_in[5];
    float* out = (float*)d_out;

    prep_queries<<<BQ / 8, 256>>>(z_rot, z_trans);
    prep_bq<<<(NB + 7) / 8, 256>>>(z_trans_book);

    const int smem_bytes = 2 * 128 * TPAD * (int)sizeof(float);
    cudaFuncSetAttribute(score_gemm, cudaFuncAttributeMaxDynamicSharedMemorySize, smem_bytes);
    dim3 grid(NBP / 128, BQ / 128, 2);
    score_gemm<<<grid, 256, smem_bytes>>>(z_rot_book, z_trans_book);

    topk_kernel<<<2 * BQ, 256>>>(rot_book, trans_book, out);
}

// round 3
// speedup vs baseline: 1.1160x; 1.1160x over previous
#include <cuda_runtime.h>
#include <cuda_fp16.h>
#include <cfloat>
#include <cstdint>

// Problem constants
#define BQ   2048
#define NB   50000
#define NBP  50048     // 391*128
#define DIM  128
#define TOPK 20

// ======================= device scratch ====================================
__device__ float g_zq[BQ];
__device__ float g_bq[NBP];
__device__ __half g_qh[2 * BQ * DIM];
__device__ __half g_ql[2 * BQ * DIM];
__device__ __half g_bh[(size_t)2 * NBP * DIM];
__device__ __half g_bl[(size_t)2 * NBP * DIM];
__device__ float g_scores[(size_t)2 * BQ * NBP];   // ~820 MB

// ======================= helpers ===========================================
__device__ __forceinline__ uint32_t smem_u32(const void* p) {
    uint32_t a;
    asm("{ .reg .u64 t; cvta.to.shared.u64 t, %1; cvt.u32.u64 %0, t; }" : "=r"(a) : "l"(p));
    return a;
}
__device__ __forceinline__ void ldsm_x4(uint32_t addr, uint32_t* r) {
    asm volatile("ldmatrix.sync.aligned.m8n8.x4.shared.b16 {%0,%1,%2,%3}, [%4];"
        : "=r"(r[0]), "=r"(r[1]), "=r"(r[2]), "=r"(r[3]) : "r"(addr));
}
__device__ __forceinline__ void mma16816(float* d, const uint32_t* a, const uint32_t* b) {
    asm volatile("mma.sync.aligned.m16n8k16.row.col.f32.f16.f16.f32 "
        "{%0,%1,%2,%3}, {%4,%5,%6,%7}, {%8,%9}, {%0,%1,%2,%3};"
        : "+f"(d[0]), "+f"(d[1]), "+f"(d[2]), "+f"(d[3])
        : "r"(a[0]), "r"(a[1]), "r"(a[2]), "r"(a[3]), "r"(b[0]), "r"(b[1]));
}
__device__ __forceinline__ void split_h(__half* hi, __half* lo, float x) {
    __half h = __float2half_rn(x);
    *hi = h;
    *lo = __float2half_rn(x - __half2float(h));
}

// ======================= prep kernels ======================================
__global__ void prep_queries(const float* __restrict__ z_rot,
                             const float* __restrict__ z_trans) {
    int warp = (blockIdx.x * blockDim.x + threadIdx.x) >> 5;
    int lane = threadIdx.x & 31;
    if (warp >= BQ) return;

    // p=0: renorm(z_rot)
    float4 v = reinterpret_cast<const float4*>(z_rot + (size_t)warp * DIM)[lane];
    float s = v.x * v.x + v.y * v.y + v.z * v.z + v.w * v.w;
    #pragma unroll
    for (int o = 16; o; o >>= 1) s += __shfl_xor_sync(0xFFFFFFFFu, s, o);
    float inv = 1.0f / sqrtf(s);
    float rv[4] = {v.x * inv, v.y * inv, v.z * inv, v.w * inv};
    size_t base0 = (size_t)warp * DIM + lane * 4;
    #pragma unroll
    for (int j = 0; j < 4; j++) split_h(g_qh + base0 + j, g_ql + base0 + j, rv[j]);

    // p=1: 2*z_trans, plus ||z||^2
    float4 t = reinterpret_cast<const float4*>(z_trans + (size_t)warp * DIM)[lane];
    float sq = t.x * t.x + t.y * t.y + t.z * t.z + t.w * t.w;
    #pragma unroll
    for (int o = 16; o; o >>= 1) sq += __shfl_xor_sync(0xFFFFFFFFu, sq, o);
    float tv[4] = {2.0f * t.x, 2.0f * t.y, 2.0f * t.z, 2.0f * t.w};
    size_t base1 = (size_t)(BQ + warp) * DIM + lane * 4;
    #pragma unroll
    for (int j = 0; j < 4; j++) split_h(g_qh + base1 + j, g_ql + base1 + j, tv[j]);
    if (lane == 0) g_zq[warp] = sq;
}

__global__ void prep_books(const float* __restrict__ z_rot_book,
                           const float* __restrict__ z_trans_book) {
    int warp = (blockIdx.x * blockDim.x + threadIdx.x) >> 5;
    int lane = threadIdx.x & 31;
    if (warp >= NBP) return;

    size_t base0 = (size_t)warp * DIM + lane * 4;
    size_t base1 = (size_t)NBP * DIM + base0;
    if (warp < NB) {
        float4 r = reinterpret_cast<const float4*>(z_rot_book + (size_t)warp * DIM)[lane];
        float rv[4] = {r.x, r.y, r.z, r.w};
        #pragma unroll
        for (int j = 0; j < 4; j++) split_h(g_bh + base0 + j, g_bl + base0 + j, rv[j]);

        float4 t = reinterpret_cast<const float4*>(z_trans_book + (size_t)warp * DIM)[lane];
        float sq = t.x * t.x + t.y * t.y + t.z * t.z + t.w * t.w;
        #pragma unroll
        for (int o = 16; o; o >>= 1) sq += __shfl_xor_sync(0xFFFFFFFFu, sq, o);
        float tv[4] = {t.x, t.y, t.z, t.w};
        #pragma unroll
        for (int j = 0; j < 4; j++) split_h(g_bh + base1 + j, g_bl + base1 + j, tv[j]);
        if (lane == 0) g_bq[warp] = sq;
    } else {
        __half z = __float2half_rn(0.0f);
        #pragma unroll
        for (int j = 0; j < 4; j++) {
            g_bh[base0 + j] = z; g_bl[base0 + j] = z;
            g_bh[base1 + j] = z; g_bl[base1 + j] = z;
        }
        if (lane == 0) g_bq[warp] = 0.0f;
    }
}

// ======================= HMMA GEMM =========================================
// CTA: 128 q x 128 n, K=128 per level. fp16 hi/lo split, 3 product passes:
// (Ah,Bh), (Ah,Bl), (Al,Bh). Error ~2^-24 relative: fp32-equivalent.
// SMEM: 4 blocks of [128 rows][128 halfs] = 32KB each, xor-swizzled.
#define SMEM_GEMM (4 * 32768 + 1024)

__global__ void __launch_bounds__(512, 1)
score_hmma() {
    extern __shared__ char smem[];
    const int tid = threadIdx.x;
    const int p     = blockIdx.z;
    const int qbase = blockIdx.y * 128;
    const int nbase = blockIdx.x * 128;

    // ---- load 4 operand blocks into swizzled smem
    const __half* srcs[4] = {
        g_qh + (size_t)(p * BQ + qbase) * DIM,
        g_ql + (size_t)(p * BQ + qbase) * DIM,
        g_bh + ((size_t)p * NBP + nbase) * DIM,
        g_bl + ((size_t)p * NBP + nbase) * DIM
    };
    #pragma unroll
    for (int b = 0; b < 4; b++) {
        char* dst = smem + b * 32768;
        const __half* src = srcs[b];
        #pragma unroll
        for (int it = 0; it < 4; it++) {
            int idx = it * 512 + tid;        // 0..2047
            int row = idx >> 4;
            int c   = idx & 15;              // 16B chunk
            uint4 v = *reinterpret_cast<const uint4*>(src + (size_t)row * DIM + c * 8);
            *reinterpret_cast<uint4*>(dst + row * 256 + ((c * 16) ^ ((row & 7) << 4))) = v;
        }
    }
    // ---- fixup vectors
    float* zqs = reinterpret_cast<float*>(smem + 131072);
    float* bqs = zqs + 128;
    if (tid < 128)       zqs[tid]       = (p == 1) ? g_zq[qbase + tid]       : 0.0f;
    else if (tid < 256)  bqs[tid - 128] = (p == 1) ? g_bq[nbase + tid - 128] : 0.0f;
    __syncthreads();

    const int lane = tid & 31;
    const int wid  = tid >> 5;
    const int wm = (wid >> 2) * 32;     // warp m base (0..96)
    const int wn = (wid & 3) * 32;      // warp n base (0..96)
    const int g  = lane >> 3;
    const int r8 = lane & 7;
    const uint32_t sx = (uint32_t)r8 << 4;
    const int aRowBase  = wm + r8 + ((g & 1) << 3);
    const int aChunkAdd = g >> 1;
    const int bRowBase  = wn + r8 + ((g >> 1) << 3);
    const int bChunkAdd = g & 1;

    uint32_t sb = smem_u32(smem);

    float d[2][4][4];
    #pragma unroll
    for (int f = 0; f < 2; f++)
        #pragma unroll
        for (int j = 0; j < 4; j++)
            #pragma unroll
            for (int e = 0; e < 4; e++) d[f][j][e] = 0.0f;

    #pragma unroll
    for (int pass = 0; pass < 3; pass++) {
        uint32_t aB = sb + (pass == 2 ? 32768u : 0u);            // Ah / Al
        uint32_t bB = sb + 65536u + (pass == 1 ? 32768u : 0u);   // Bh / Bl
        #pragma unroll
        for (int s = 0; s < 8; s++) {
            uint32_t a[2][4], b[2][4];
            #pragma unroll
            for (int f = 0; f < 2; f++) {
                int row = aRowBase + f * 16;
                uint32_t ch = (uint32_t)(2 * s + aChunkAdd);
                ldsm_x4(aB + row * 256 + ((ch << 4) ^ sx), a[f]);
            }
            #pragma unroll
            for (int h = 0; h < 2; h++) {
                int row = bRowBase + h * 16;
                uint32_t ch = (uint32_t)(2 * s + bChunkAdd);
                ldsm_x4(bB + row * 256 + ((ch << 4) ^ sx), b[h]);
            }
            #pragma unroll
            for (int f = 0; f < 2; f++)
                #pragma unroll
                for (int j = 0; j < 4; j++)
                    mma16816(d[f][j], a[f], &b[j >> 1][(j & 1) * 2]);
        }
    }

    // ---- epilogue: fixups + store
    float* S = g_scores + ((size_t)p * BQ + qbase) * NBP + nbase;
    #pragma unroll
    for (int f = 0; f < 2; f++) {
        int mA = wm + f * 16 + (lane >> 2);
        int mB = mA + 8;
        float zqA = zqs[mA], zqB = zqs[mB];
        #pragma unroll
        for (int j = 0; j < 4; j++) {
            int n = wn + j * 8 + (lane & 3) * 2;
            float b0 = bqs[n], b1 = bqs[n + 1];
            float2 v0 = make_float2(d[f][j][0] - zqA - b0, d[f][j][1] - zqA - b1);
            float2 v1 = make_float2(d[f][j][2] - zqB - b0, d[f][j][3] - zqB - b1);
            *reinterpret_cast<float2*>(S + (size_t)mA * NBP + n) = v0;
            *reinterpret_cast<float2*>(S + (size_t)mB * NBP + n) = v1;
        }
    }
}

// ======================= top-k + gather ====================================
__global__ void __launch_bounds__(256)
topk_kernel(const float* __restrict__ rot_book,
            const float* __restrict__ trans_book,
            float* __restrict__ out) {
    const int p   = blockIdx.x >> 11;
    const int r   = blockIdx.x & 2047;
    const int tid = threadIdx.x;
    const float* s = g_scores + ((size_t)p * BQ + r) * NBP;

    float lv[TOPK];
    int   li[TOPK];
    #pragma unroll
    for (int t = 0; t < TOPK; t++) { lv[t] = -FLT_MAX; li[t] = 0x7FFFFFFF; }
    float vmin = -FLT_MAX; int minidx = 0x7FFFFFFF; int minslot = 0;

    for (int n = tid; n < NB; n += 256) {
        float v = s[n];
        if (v > vmin || (v == vmin && n < minidx)) {
            #pragma unroll
            for (int t = 0; t < TOPK; t++)
                if (t == minslot) { lv[t] = v; li[t] = n; }
            vmin = lv[0]; minidx = li[0]; minslot = 0;
            #pragma unroll
            for (int t = 1; t < TOPK; t++)
                if (lv[t] < vmin || (lv[t] == vmin && li[t] > minidx)) {
                    vmin = lv[t]; minidx = li[t]; minslot = t;
                }
        }
    }

    __shared__ float sv[256 * TOPK];
    __shared__ int   si[256 * TOPK];
    __shared__ float wv[8];
    __shared__ int   wi[8], wp[8];

    #pragma unroll
    for (int t = 0; t < TOPK; t++) {
        sv[tid * TOPK + t] = lv[t];
        si[tid * TOPK + t] = li[t];
    }
    __syncthreads();

    const size_t BK = (size_t)BQ * TOPK;

    for (int k = 0; k < TOPK; k++) {
        float bv = -FLT_MAX; int bi = 0x7FFFFFFF; int bp = 0;
        #pragma unroll
        for (int e = 0; e < TOPK; e++) {
            int pos = tid + e * 256;
            float v = sv[pos]; int ii = si[pos];
            if (v > bv || (v == bv && ii < bi)) { bv = v; bi = ii; bp = pos; }
        }
        #pragma unroll
        for (int o = 16; o; o >>= 1) {
            float ov = __shfl_down_sync(0xFFFFFFFFu, bv, o);
            int   oi = __shfl_down_sync(0xFFFFFFFFu, bi, o);
            int   op = __shfl_down_sync(0xFFFFFFFFu, bp, o);
            if (ov > bv || (ov == bv && oi < bi)) { bv = ov; bi = oi; bp = op; }
        }
        if ((tid & 31) == 0) { int w = tid >> 5; wv[w] = bv; wi[w] = bi; wp[w] = bp; }
        __syncthreads();
        if (tid == 0) {
            float gv = wv[0]; int gi = wi[0]; int gp = wp[0];
            #pragma unroll
            for (int w = 1; w < 8; w++)
                if (wv[w] > gv || (wv[w] == gv && wi[w] < gi)) { gv = wv[w]; gi = wi[w]; gp = wp[w]; }
            sv[gp] = -FLT_MAX; si[gp] = 0x7FFFFFFF;
            size_t rk = (size_t)r * TOPK + k;
            if (p == 0) {
                out[rk]          = gv;
                out[BK + rk]     = (float)gi;
                out[2 * BK + rk] = rot_book[gi];
            } else {
                out[3 * BK + rk] = gv;
                out[4 * BK + rk] = (float)gi;
                out[5 * BK + rk * 3 + 0] = trans_book[(size_t)gi * 3 + 0];
                out[5 * BK + rk * 3 + 1] = trans_book[(size_t)gi * 3 + 1];
                out[5 * BK + rk * 3 + 2] = trans_book[(size_t)gi * 3 + 2];
            }
        }
        __syncthreads();
    }
}

// ======================= launch ============================================
extern "C" void kernel_launch(void* const* d_in, const int* in_sizes, int n_in,
                              void* d_out, int out_size) {
    const float* z_rot        = (const float*)d_in[0];
    const float* z_trans      = (const float*)d_in[1];
    const float* z_rot_book   = (const float*)d_in[2];
    const float* z_trans_book = (const float*)d_in[3];
    const float* rot_book     = (const float*)d_in[4];
    const float* trans_book   = (const float*)d_in[5];
    float* out = (float*)d_out;

    prep_queries<<<BQ / 8, 256>>>(z_rot, z_trans);
    prep_books<<<(NBP + 7) / 8, 256>>>(z_rot_book, z_trans_book);

    cudaFuncSetAttribute(score_hmma, cudaFuncAttributeMaxDynamicSharedMemorySize, SMEM_GEMM);
    dim3 grid(NBP / 128, BQ / 128, 2);
    score_hmma<<<grid, 512, SMEM_GEMM>>>();

    topk_kernel<<<2 * BQ, 256>>>(rot_book, trans_book, out);
}

// round 4
// speedup vs baseline: 1.1174x; 1.0012x over previous
#include <cuda_runtime.h>
#include <cuda_fp16.h>
#include <cfloat>
#include <cstdint>

// Problem constants
#define BQ   2048
#define NB   50000
#define NBP  50048     // 391*128
#define DIM  128
#define TOPK 20

// ======================= device scratch ====================================
__device__ float g_zq[BQ];
__device__ float g_bq[NBP];
__device__ __half g_qh[2 * BQ * DIM];
__device__ __half g_ql[2 * BQ * DIM];
__device__ __half g_bh[(size_t)2 * NBP * DIM];
__device__ __half g_bl[(size_t)2 * NBP * DIM];
__device__ float g_scores[(size_t)2 * BQ * NBP];   // ~820 MB

// ======================= helpers ===========================================
__device__ __forceinline__ uint32_t smem_u32(const void* p) {
    uint32_t a;
    asm("{ .reg .u64 t; cvta.to.shared.u64 t, %1; cvt.u32.u64 %0, t; }" : "=r"(a) : "l"(p));
    return a;
}
__device__ __forceinline__ void ldsm_x4(uint32_t addr, uint32_t* r) {
    asm volatile("ldmatrix.sync.aligned.m8n8.x4.shared.b16 {%0,%1,%2,%3}, [%4];"
        : "=r"(r[0]), "=r"(r[1]), "=r"(r[2]), "=r"(r[3]) : "r"(addr));
}
__device__ __forceinline__ void mma16816(float* d, const uint32_t* a, const uint32_t* b) {
    asm volatile("mma.sync.aligned.m16n8k16.row.col.f32.f16.f16.f32 "
        "{%0,%1,%2,%3}, {%4,%5,%6,%7}, {%8,%9}, {%0,%1,%2,%3};"
        : "+f"(d[0]), "+f"(d[1]), "+f"(d[2]), "+f"(d[3])
        : "r"(a[0]), "r"(a[1]), "r"(a[2]), "r"(a[3]), "r"(b[0]), "r"(b[1]));
}
__device__ __forceinline__ void split_h(__half* hi, __half* lo, float x) {
    __half h = __float2half_rn(x);
    *hi = h;
    *lo = __float2half_rn(x - __half2float(h));
}

// ======================= prep kernels ======================================
__global__ void prep_queries(const float* __restrict__ z_rot,
                             const float* __restrict__ z_trans) {
    int warp = (blockIdx.x * blockDim.x + threadIdx.x) >> 5;
    int lane = threadIdx.x & 31;
    if (warp >= BQ) return;

    // p=0: renorm(z_rot)
    float4 v = reinterpret_cast<const float4*>(z_rot + (size_t)warp * DIM)[lane];
    float s = v.x * v.x + v.y * v.y + v.z * v.z + v.w * v.w;
    #pragma unroll
    for (int o = 16; o; o >>= 1) s += __shfl_xor_sync(0xFFFFFFFFu, s, o);
    float inv = 1.0f / sqrtf(s);
    float rv[4] = {v.x * inv, v.y * inv, v.z * inv, v.w * inv};
    size_t base0 = (size_t)warp * DIM + lane * 4;
    #pragma unroll
    for (int j = 0; j < 4; j++) split_h(g_qh + base0 + j, g_ql + base0 + j, rv[j]);

    // p=1: 2*z_trans, plus ||z||^2
    float4 t = reinterpret_cast<const float4*>(z_trans + (size_t)warp * DIM)[lane];
    float sq = t.x * t.x + t.y * t.y + t.z * t.z + t.w * t.w;
    #pragma unroll
    for (int o = 16; o; o >>= 1) sq += __shfl_xor_sync(0xFFFFFFFFu, sq, o);
    float tv[4] = {2.0f * t.x, 2.0f * t.y, 2.0f * t.z, 2.0f * t.w};
    size_t base1 = (size_t)(BQ + warp) * DIM + lane * 4;
    #pragma unroll
    for (int j = 0; j < 4; j++) split_h(g_qh + base1 + j, g_ql + base1 + j, tv[j]);
    if (lane == 0) g_zq[warp] = sq;
}

__global__ void prep_books(const float* __restrict__ z_rot_book,
                           const float* __restrict__ z_trans_book) {
    int warp = (blockIdx.x * blockDim.x + threadIdx.x) >> 5;
    int lane = threadIdx.x & 31;
    if (warp >= NBP) return;

    size_t base0 = (size_t)warp * DIM + lane * 4;
    size_t base1 = (size_t)NBP * DIM + base0;
    if (warp < NB) {
        float4 r = reinterpret_cast<const float4*>(z_rot_book + (size_t)warp * DIM)[lane];
        float rv[4] = {r.x, r.y, r.z, r.w};
        #pragma unroll
        for (int j = 0; j < 4; j++) split_h(g_bh + base0 + j, g_bl + base0 + j, rv[j]);

        float4 t = reinterpret_cast<const float4*>(z_trans_book + (size_t)warp * DIM)[lane];
        float sq = t.x * t.x + t.y * t.y + t.z * t.z + t.w * t.w;
        #pragma unroll
        for (int o = 16; o; o >>= 1) sq += __shfl_xor_sync(0xFFFFFFFFu, sq, o);
        float tv[4] = {t.x, t.y, t.z, t.w};
        #pragma unroll
        for (int j = 0; j < 4; j++) split_h(g_bh + base1 + j, g_bl + base1 + j, tv[j]);
        if (lane == 0) g_bq[warp] = sq;
    } else {
        __half z = __float2half_rn(0.0f);
        #pragma unroll
        for (int j = 0; j < 4; j++) {
            g_bh[base0 + j] = z; g_bl[base0 + j] = z;
            g_bh[base1 + j] = z; g_bl[base1 + j] = z;
        }
        if (lane == 0) g_bq[warp] = 0.0f;
    }
}

// ======================= HMMA GEMM =========================================
// CTA: 128 q x 128 n, K=128 per level. fp16 hi/lo split, 3 product passes:
// (Ah,Bh), (Ah,Bl), (Al,Bh). Error ~2^-24 relative: fp32-equivalent.
// SMEM: 4 blocks of [128 rows][128 halfs] = 32KB each, xor-swizzled.
#define SMEM_GEMM (4 * 32768 + 1024)

__global__ void __launch_bounds__(512, 1)
score_hmma() {
    extern __shared__ char smem[];
    const int tid = threadIdx.x;
    const int p     = blockIdx.z;
    const int qbase = blockIdx.y * 128;
    const int nbase = blockIdx.x * 128;

    // ---- load 4 operand blocks into swizzled smem
    const __half* srcs[4] = {
        g_qh + (size_t)(p * BQ + qbase) * DIM,
        g_ql + (size_t)(p * BQ + qbase) * DIM,
        g_bh + ((size_t)p * NBP + nbase) * DIM,
        g_bl + ((size_t)p * NBP + nbase) * DIM
    };
    #pragma unroll
    for (int b = 0; b < 4; b++) {
        char* dst = smem + b * 32768;
        const __half* src = srcs[b];
        #pragma unroll
        for (int it = 0; it < 4; it++) {
            int idx = it * 512 + tid;        // 0..2047
            int row = idx >> 4;
            int c   = idx & 15;              // 16B chunk
            uint4 v = *reinterpret_cast<const uint4*>(src + (size_t)row * DIM + c * 8);
            *reinterpret_cast<uint4*>(dst + row * 256 + ((c * 16) ^ ((row & 7) << 4))) = v;
        }
    }
    // ---- fixup vectors
    float* zqs = reinterpret_cast<float*>(smem + 131072);
    float* bqs = zqs + 128;
    if (tid < 128)       zqs[tid]       = (p == 1) ? g_zq[qbase + tid]       : 0.0f;
    else if (tid < 256)  bqs[tid - 128] = (p == 1) ? g_bq[nbase + tid - 128] : 0.0f;
    __syncthreads();

    const int lane = tid & 31;
    const int wid  = tid >> 5;
    const int wm = (wid >> 2) * 32;     // warp m base (0..96)
    const int wn = (wid & 3) * 32;      // warp n base (0..96)
    const int g  = lane >> 3;
    const int r8 = lane & 7;
    const uint32_t sx = (uint32_t)r8 << 4;
    const int aRowBase  = wm + r8 + ((g & 1) << 3);
    const int aChunkAdd = g >> 1;
    const int bRowBase  = wn + r8 + ((g >> 1) << 3);
    const int bChunkAdd = g & 1;

    uint32_t sb = smem_u32(smem);

    float d[2][4][4];
    #pragma unroll
    for (int f = 0; f < 2; f++)
        #pragma unroll
        for (int j = 0; j < 4; j++)
            #pragma unroll
            for (int e = 0; e < 4; e++) d[f][j][e] = 0.0f;

    #pragma unroll
    for (int pass = 0; pass < 3; pass++) {
        uint32_t aB = sb + (pass == 2 ? 32768u : 0u);            // Ah / Al
        uint32_t bB = sb + 65536u + (pass == 1 ? 32768u : 0u);   // Bh / Bl
        #pragma unroll
        for (int s = 0; s < 8; s++) {
            uint32_t a[2][4], b[2][4];
            #pragma unroll
            for (int f = 0; f < 2; f++) {
                int row = aRowBase + f * 16;
                uint32_t ch = (uint32_t)(2 * s + aChunkAdd);
                ldsm_x4(aB + row * 256 + ((ch << 4) ^ sx), a[f]);
            }
            #pragma unroll
            for (int h = 0; h < 2; h++) {
                int row = bRowBase + h * 16;
                uint32_t ch = (uint32_t)(2 * s + bChunkAdd);
                ldsm_x4(bB + row * 256 + ((ch << 4) ^ sx), b[h]);
            }
            #pragma unroll
            for (int f = 0; f < 2; f++)
                #pragma unroll
                for (int j = 0; j < 4; j++)
                    mma16816(d[f][j], a[f], &b[j >> 1][(j & 1) * 2]);
        }
    }

    // ---- epilogue: fixups + store
    float* S = g_scores + ((size_t)p * BQ + qbase) * NBP + nbase;
    #pragma unroll
    for (int f = 0; f < 2; f++) {
        int mA = wm + f * 16 + (lane >> 2);
        int mB = mA + 8;
        float zqA = zqs[mA], zqB = zqs[mB];
        #pragma unroll
        for (int j = 0; j < 4; j++) {
            int n = wn + j * 8 + (lane & 3) * 2;
            float b0 = bqs[n], b1 = bqs[n + 1];
            float2 v0 = make_float2(d[f][j][0] - zqA - b0, d[f][j][1] - zqA - b1);
            float2 v1 = make_float2(d[f][j][2] - zqB - b0, d[f][j][3] - zqB - b1);
            *reinterpret_cast<float2*>(S + (size_t)mA * NBP + n) = v0;
            *reinterpret_cast<float2*>(S + (size_t)mB * NBP + n) = v1;
        }
    }
}

// ======================= top-k + gather ====================================
__global__ void __launch_bounds__(256)
topk_kernel(const float* __restrict__ rot_book,
            const float* __restrict__ trans_book,
            float* __restrict__ out) {
    const int p   = blockIdx.x >> 11;
    const int r   = blockIdx.x & 2047;
    const int tid = threadIdx.x;
    const float* s = g_scores + ((size_t)p * BQ + r) * NBP;

    float lv[TOPK];
    int   li[TOPK];
    #pragma unroll
    for (int t = 0; t < TOPK; t++) { lv[t] = -FLT_MAX; li[t] = 0x7FFFFFFF; }
    float vmin = -FLT_MAX; int minidx = 0x7FFFFFFF; int minslot = 0;

    for (int n = tid; n < NB; n += 256) {
        float v = s[n];
        if (v > vmin || (v == vmin && n < minidx)) {
            #pragma unroll
            for (int t = 0; t < TOPK; t++)
                if (t == minslot) { lv[t] = v; li[t] = n; }
            vmin = lv[0]; minidx = li[0]; minslot = 0;
            #pragma unroll
            for (int t = 1; t < TOPK; t++)
                if (lv[t] < vmin || (lv[t] == vmin && li[t] > minidx)) {
                    vmin = lv[t]; minidx = li[t]; minslot = t;
                }
        }
    }

    __shared__ float sv[256 * TOPK];
    __shared__ int   si[256 * TOPK];
    __shared__ float wv[8];
    __shared__ int   wi[8], wp[8];

    #pragma unroll
    for (int t = 0; t < TOPK; t++) {
        sv[tid * TOPK + t] = lv[t];
        si[tid * TOPK + t] = li[t];
    }
    __syncthreads();

    const size_t BK = (size_t)BQ * TOPK;

    for (int k = 0; k < TOPK; k++) {
        float bv = -FLT_MAX; int bi = 0x7FFFFFFF; int bp = 0;
        #pragma unroll
        for (int e = 0; e < TOPK; e++) {
            int pos = tid + e * 256;
            float v = sv[pos]; int ii = si[pos];
            if (v > bv || (v == bv && ii < bi)) { bv = v; bi = ii; bp = pos; }
        }
        #pragma unroll
        for (int o = 16; o; o >>= 1) {
            float ov = __shfl_down_sync(0xFFFFFFFFu, bv, o);
            int   oi = __shfl_down_sync(0xFFFFFFFFu, bi, o);
            int   op = __shfl_down_sync(0xFFFFFFFFu, bp, o);
            if (ov > bv || (ov == bv && oi < bi)) { bv = ov; bi = oi; bp = op; }
        }
        if ((tid & 31) == 0) { int w = tid >> 5; wv[w] = bv; wi[w] = bi; wp[w] = bp; }
        __syncthreads();
        if (tid == 0) {
            float gv = wv[0]; int gi = wi[0]; int gp = wp[0];
            #pragma unroll
            for (int w = 1; w < 8; w++)
                if (wv[w] > gv || (wv[w] == gv && wi[w] < gi)) { gv = wv[w]; gi = wi[w]; gp = wp[w]; }
            sv[gp] = -FLT_MAX; si[gp] = 0x7FFFFFFF;
            size_t rk = (size_t)r * TOPK + k;
            if (p == 0) {
                out[rk]          = gv;
                out[BK + rk]     = (float)gi;
                out[2 * BK + rk] = rot_book[gi];
            } else {
                out[3 * BK + rk] = gv;
                out[4 * BK + rk] = (float)gi;
                out[5 * BK + rk * 3 + 0] = trans_book[(size_t)gi * 3 + 0];
                out[5 * BK + rk * 3 + 1] = trans_book[(size_t)gi * 3 + 1];
                out[5 * BK + rk * 3 + 2] = trans_book[(size_t)gi * 3 + 2];
            }
        }
        __syncthreads();
    }
}

// ======================= launch ============================================
extern "C" void kernel_launch(void* const* d_in, const int* in_sizes, int n_in,
                              void* d_out, int out_size) {
    const float* z_rot        = (const float*)d_in[0];
    const float* z_trans      = (const float*)d_in[1];
    const float* z_rot_book   = (const float*)d_in[2];
    const float* z_trans_book = (const float*)d_in[3];
    const float* rot_book     = (const float*)d_in[4];
    const float* trans_book   = (const float*)d_in[5];
    float* out = (float*)d_out;

    prep_queries<<<BQ / 8, 256>>>(z_rot, z_trans);
    prep_books<<<(NBP + 7) / 8, 256>>>(z_rot_book, z_trans_book);

    cudaFuncSetAttribute(score_hmma, cudaFuncAttributeMaxDynamicSharedMemorySize, SMEM_GEMM);
    dim3 grid(NBP / 128, BQ / 128, 2);
    score_hmma<<<grid, 512, SMEM_GEMM>>>();

    topk_kernel<<<2 * BQ, 256>>>(rot_book, trans_book, out);
}

// round 5
// speedup vs baseline: 1.1175x; 1.0001x over previous
#include <cuda_runtime.h>
#include <cuda_fp16.h>
#include <cfloat>
#include <cstdint>

// Problem constants
#define BQ   2048
#define NB   50000
#define NBP  50048     // 391*128
#define DIM  128
#define TOPK 20

// ======================= device scratch ====================================
__device__ float g_zq[BQ];
__device__ float g_bq[NBP];
__device__ __half g_qh[2 * BQ * DIM];
__device__ __half g_ql[2 * BQ * DIM];
__device__ __half g_bh[(size_t)2 * NBP * DIM];
__device__ __half g_bl[(size_t)2 * NBP * DIM];
__device__ float g_scores[(size_t)2 * BQ * NBP];   // ~820 MB

// ======================= helpers ===========================================
__device__ __forceinline__ uint32_t smem_u32(const void* p) {
    uint32_t a;
    asm("{ .reg .u64 t; cvta.to.shared.u64 t, %1; cvt.u32.u64 %0, t; }" : "=r"(a) : "l"(p));
    return a;
}
__device__ __forceinline__ void ldsm_x4(uint32_t addr, uint32_t* r) {
    asm volatile("ldmatrix.sync.aligned.m8n8.x4.shared.b16 {%0,%1,%2,%3}, [%4];"
        : "=r"(r[0]), "=r"(r[1]), "=r"(r[2]), "=r"(r[3]) : "r"(addr));
}
__device__ __forceinline__ void mma16816(float* d, const uint32_t* a, const uint32_t* b) {
    asm volatile("mma.sync.aligned.m16n8k16.row.col.f32.f16.f16.f32 "
        "{%0,%1,%2,%3}, {%4,%5,%6,%7}, {%8,%9}, {%0,%1,%2,%3};"
        : "+f"(d[0]), "+f"(d[1]), "+f"(d[2]), "+f"(d[3])
        : "r"(a[0]), "r"(a[1]), "r"(a[2]), "r"(a[3]), "r"(b[0]), "r"(b[1]));
}
__device__ __forceinline__ void split_h(__half* hi, __half* lo, float x) {
    __half h = __float2half_rn(x);
    *hi = h;
    *lo = __float2half_rn(x - __half2float(h));
}

// ======================= prep kernels ======================================
__global__ void prep_queries(const float* __restrict__ z_rot,
                             const float* __restrict__ z_trans) {
    int warp = (blockIdx.x * blockDim.x + threadIdx.x) >> 5;
    int lane = threadIdx.x & 31;
    if (warp >= BQ) return;

    // p=0: renorm(z_rot)
    float4 v = reinterpret_cast<const float4*>(z_rot + (size_t)warp * DIM)[lane];
    float s = v.x * v.x + v.y * v.y + v.z * v.z + v.w * v.w;
    #pragma unroll
    for (int o = 16; o; o >>= 1) s += __shfl_xor_sync(0xFFFFFFFFu, s, o);
    float inv = 1.0f / sqrtf(s);
    float rv[4] = {v.x * inv, v.y * inv, v.z * inv, v.w * inv};
    size_t base0 = (size_t)warp * DIM + lane * 4;
    #pragma unroll
    for (int j = 0; j < 4; j++) split_h(g_qh + base0 + j, g_ql + base0 + j, rv[j]);

    // p=1: 2*z_trans, plus ||z||^2
    float4 t = reinterpret_cast<const float4*>(z_trans + (size_t)warp * DIM)[lane];
    float sq = t.x * t.x + t.y * t.y + t.z * t.z + t.w * t.w;
    #pragma unroll
    for (int o = 16; o; o >>= 1) sq += __shfl_xor_sync(0xFFFFFFFFu, sq, o);
    float tv[4] = {2.0f * t.x, 2.0f * t.y, 2.0f * t.z, 2.0f * t.w};
    size_t base1 = (size_t)(BQ + warp) * DIM + lane * 4;
    #pragma unroll
    for (int j = 0; j < 4; j++) split_h(g_qh + base1 + j, g_ql + base1 + j, tv[j]);
    if (lane == 0) g_zq[warp] = sq;
}

__global__ void prep_books(const float* __restrict__ z_rot_book,
                           const float* __restrict__ z_trans_book) {
    int warp = (blockIdx.x * blockDim.x + threadIdx.x) >> 5;
    int lane = threadIdx.x & 31;
    if (warp >= NBP) return;

    size_t base0 = (size_t)warp * DIM + lane * 4;
    size_t base1 = (size_t)NBP * DIM + base0;
    if (warp < NB) {
        float4 r = reinterpret_cast<const float4*>(z_rot_book + (size_t)warp * DIM)[lane];
        float rv[4] = {r.x, r.y, r.z, r.w};
        #pragma unroll
        for (int j = 0; j < 4; j++) split_h(g_bh + base0 + j, g_bl + base0 + j, rv[j]);

        float4 t = reinterpret_cast<const float4*>(z_trans_book + (size_t)warp * DIM)[lane];
        float sq = t.x * t.x + t.y * t.y + t.z * t.z + t.w * t.w;
        #pragma unroll
        for (int o = 16; o; o >>= 1) sq += __shfl_xor_sync(0xFFFFFFFFu, sq, o);
        float tv[4] = {t.x, t.y, t.z, t.w};
        #pragma unroll
        for (int j = 0; j < 4; j++) split_h(g_bh + base1 + j, g_bl + base1 + j, tv[j]);
        if (lane == 0) g_bq[warp] = sq;
    } else {
        __half z = __float2half_rn(0.0f);
        #pragma unroll
        for (int j = 0; j < 4; j++) {
            g_bh[base0 + j] = z; g_bl[base0 + j] = z;
            g_bh[base1 + j] = z; g_bl[base1 + j] = z;
        }
        if (lane == 0) g_bq[warp] = 0.0f;
    }
}

// ======================= HMMA GEMM =========================================
// CTA: 128 q x 128 n, K=128 per level. fp16 hi/lo split, 3 product passes:
// (Ah,Bh), (Ah,Bl), (Al,Bh). Error ~2^-24 relative: fp32-equivalent.
// SMEM: 4 blocks of [128 rows][128 halfs] = 32KB each, xor-swizzled.
#define SMEM_GEMM (4 * 32768 + 1024)

__global__ void __launch_bounds__(512, 1)
score_hmma() {
    extern __shared__ char smem[];
    const int tid = threadIdx.x;
    const int p     = blockIdx.z;
    const int qbase = blockIdx.y * 128;
    const int nbase = blockIdx.x * 128;

    // ---- load 4 operand blocks into swizzled smem
    const __half* srcs[4] = {
        g_qh + (size_t)(p * BQ + qbase) * DIM,
        g_ql + (size_t)(p * BQ + qbase) * DIM,
        g_bh + ((size_t)p * NBP + nbase) * DIM,
        g_bl + ((size_t)p * NBP + nbase) * DIM
    };
    #pragma unroll
    for (int b = 0; b < 4; b++) {
        char* dst = smem + b * 32768;
        const __half* src = srcs[b];
        #pragma unroll
        for (int it = 0; it < 4; it++) {
            int idx = it * 512 + tid;        // 0..2047
            int row = idx >> 4;
            int c   = idx & 15;              // 16B chunk
            uint4 v = *reinterpret_cast<const uint4*>(src + (size_t)row * DIM + c * 8);
            *reinterpret_cast<uint4*>(dst + row * 256 + ((c * 16) ^ ((row & 7) << 4))) = v;
        }
    }
    // ---- fixup vectors
    float* zqs = reinterpret_cast<float*>(smem + 131072);
    float* bqs = zqs + 128;
    if (tid < 128)       zqs[tid]       = (p == 1) ? g_zq[qbase + tid]       : 0.0f;
    else if (tid < 256)  bqs[tid - 128] = (p == 1) ? g_bq[nbase + tid - 128] : 0.0f;
    __syncthreads();

    const int lane = tid & 31;
    const int wid  = tid >> 5;
    const int wm = (wid >> 2) * 32;     // warp m base (0..96)
    const int wn = (wid & 3) * 32;      // warp n base (0..96)
    const int g  = lane >> 3;
    const int r8 = lane & 7;
    const uint32_t sx = (uint32_t)r8 << 4;
    const int aRowBase  = wm + r8 + ((g & 1) << 3);
    const int aChunkAdd = g >> 1;
    const int bRowBase  = wn + r8 + ((g >> 1) << 3);
    const int bChunkAdd = g & 1;

    uint32_t sb = smem_u32(smem);

    float d[2][4][4];
    #pragma unroll
    for (int f = 0; f < 2; f++)
        #pragma unroll
        for (int j = 0; j < 4; j++)
            #pragma unroll
            for (int e = 0; e < 4; e++) d[f][j][e] = 0.0f;

    #pragma unroll
    for (int pass = 0; pass < 3; pass++) {
        uint32_t aB = sb + (pass == 2 ? 32768u : 0u);            // Ah / Al
        uint32_t bB = sb + 65536u + (pass == 1 ? 32768u : 0u);   // Bh / Bl
        #pragma unroll
        for (int s = 0; s < 8; s++) {
            uint32_t a[2][4], b[2][4];
            #pragma unroll
            for (int f = 0; f < 2; f++) {
                int row = aRowBase + f * 16;
                uint32_t ch = (uint32_t)(2 * s + aChunkAdd);
                ldsm_x4(aB + row * 256 + ((ch << 4) ^ sx), a[f]);
            }
            #pragma unroll
            for (int h = 0; h < 2; h++) {
                int row = bRowBase + h * 16;
                uint32_t ch = (uint32_t)(2 * s + bChunkAdd);
                ldsm_x4(bB + row * 256 + ((ch << 4) ^ sx), b[h]);
            }
            #pragma unroll
            for (int f = 0; f < 2; f++)
                #pragma unroll
                for (int j = 0; j < 4; j++)
                    mma16816(d[f][j], a[f], &b[j >> 1][(j & 1) * 2]);
        }
    }

    // ---- epilogue: fixups + store
    float* S = g_scores + ((size_t)p * BQ + qbase) * NBP + nbase;
    #pragma unroll
    for (int f = 0; f < 2; f++) {
        int mA = wm + f * 16 + (lane >> 2);
        int mB = mA + 8;
        float zqA = zqs[mA], zqB = zqs[mB];
        #pragma unroll
        for (int j = 0; j < 4; j++) {
            int n = wn + j * 8 + (lane & 3) * 2;
            float b0 = bqs[n], b1 = bqs[n + 1];
            float2 v0 = make_float2(d[f][j][0] - zqA - b0, d[f][j][1] - zqA - b1);
            float2 v1 = make_float2(d[f][j][2] - zqB - b0, d[f][j][3] - zqB - b1);
            *reinterpret_cast<float2*>(S + (size_t)mA * NBP + n) = v0;
            *reinterpret_cast<float2*>(S + (size_t)mB * NBP + n) = v1;
        }
    }
}

// ======================= top-k + gather ====================================
__global__ void __launch_bounds__(256)
topk_kernel(const float* __restrict__ rot_book,
            const float* __restrict__ trans_book,
            float* __restrict__ out) {
    const int p   = blockIdx.x >> 11;
    const int r   = blockIdx.x & 2047;
    const int tid = threadIdx.x;
    const float* s = g_scores + ((size_t)p * BQ + r) * NBP;

    float lv[TOPK];
    int   li[TOPK];
    #pragma unroll
    for (int t = 0; t < TOPK; t++) { lv[t] = -FLT_MAX; li[t] = 0x7FFFFFFF; }
    float vmin = -FLT_MAX; int minidx = 0x7FFFFFFF; int minslot = 0;

    for (int n = tid; n < NB; n += 256) {
        float v = s[n];
        if (v > vmin || (v == vmin && n < minidx)) {
            #pragma unroll
            for (int t = 0; t < TOPK; t++)
                if (t == minslot) { lv[t] = v; li[t] = n; }
            vmin = lv[0]; minidx = li[0]; minslot = 0;
            #pragma unroll
            for (int t = 1; t < TOPK; t++)
                if (lv[t] < vmin || (lv[t] == vmin && li[t] > minidx)) {
                    vmin = lv[t]; minidx = li[t]; minslot = t;
                }
        }
    }

    __shared__ float sv[256 * TOPK];
    __shared__ int   si[256 * TOPK];
    __shared__ float wv[8];
    __shared__ int   wi[8], wp[8];

    #pragma unroll
    for (int t = 0; t < TOPK; t++) {
        sv[tid * TOPK + t] = lv[t];
        si[tid * TOPK + t] = li[t];
    }
    __syncthreads();

    const size_t BK = (size_t)BQ * TOPK;

    for (int k = 0; k < TOPK; k++) {
        float bv = -FLT_MAX; int bi = 0x7FFFFFFF; int bp = 0;
        #pragma unroll
        for (int e = 0; e < TOPK; e++) {
            int pos = tid + e * 256;
            float v = sv[pos]; int ii = si[pos];
            if (v > bv || (v == bv && ii < bi)) { bv = v; bi = ii; bp = pos; }
        }
        #pragma unroll
        for (int o = 16; o; o >>= 1) {
            float ov = __shfl_down_sync(0xFFFFFFFFu, bv, o);
            int   oi = __shfl_down_sync(0xFFFFFFFFu, bi, o);
            int   op = __shfl_down_sync(0xFFFFFFFFu, bp, o);
            if (ov > bv || (ov == bv && oi < bi)) { bv = ov; bi = oi; bp = op; }
        }
        if ((tid & 31) == 0) { int w = tid >> 5; wv[w] = bv; wi[w] = bi; wp[w] = bp; }
        __syncthreads();
        if (tid == 0) {
            float gv = wv[0]; int gi = wi[0]; int gp = wp[0];
            #pragma unroll
            for (int w = 1; w < 8; w++)
                if (wv[w] > gv || (wv[w] == gv && wi[w] < gi)) { gv = wv[w]; gi = wi[w]; gp = wp[w]; }
            sv[gp] = -FLT_MAX; si[gp] = 0x7FFFFFFF;
            size_t rk = (size_t)r * TOPK + k;
            if (p == 0) {
                out[rk]          = gv;
                out[BK + rk]     = (float)gi;
                out[2 * BK + rk] = rot_book[gi];
            } else {
                out[3 * BK + rk] = gv;
                out[4 * BK + rk] = (float)gi;
                out[5 * BK + rk * 3 + 0] = trans_book[(size_t)gi * 3 + 0];
                out[5 * BK + rk * 3 + 1] = trans_book[(size_t)gi * 3 + 1];
                out[5 * BK + rk * 3 + 2] = trans_book[(size_t)gi * 3 + 2];
            }
        }
        __syncthreads();
    }
}

// ======================= launch ============================================
extern "C" void kernel_launch(void* const* d_in, const int* in_sizes, int n_in,
                              void* d_out, int out_size) {
    const float* z_rot        = (const float*)d_in[0];
    const float* z_trans      = (const float*)d_in[1];
    const float* z_rot_book   = (const float*)d_in[2];
    const float* z_trans_book = (const float*)d_in[3];
    const float* rot_book     = (const float*)d_in[4];
    const float* trans_book   = (const float*)d_in[5];
    float* out = (float*)d_out;

    prep_queries<<<BQ / 8, 256>>>(z_rot, z_trans);
    prep_books<<<(NBP + 7) / 8, 256>>>(z_rot_book, z_trans_book);

    cudaFuncSetAttribute(score_hmma, cudaFuncAttributeMaxDynamicSharedMemorySize, SMEM_GEMM);
    dim3 grid(NBP / 128, BQ / 128, 2);
    score_hmma<<<grid, 512, SMEM_GEMM>>>();

    topk_kernel<<<2 * BQ, 256>>>(rot_book, trans_book, out);
}

// round 6
// speedup vs baseline: 3.4808x; 3.1149x over previous
#include <cuda_runtime.h>
#include <cuda_fp16.h>
#include <cfloat>
#include <cstdint>

// Problem constants
#define BQ    2048
#define NB    50000
#define NBP   50048     // 391*128
#define DIM   128
#define TOPK  20
#define NCAND 32

// ======================= device scratch ====================================
__device__ float  g_zq[BQ];
__device__ float  g_bq[NBP];
__device__ float  g_qf[2 * BQ * DIM];                 // staged fp32 queries (renorm zr / 2*zt)
__device__ __half g_qh16[2 * BQ * DIM];               // fp16 staged queries
__device__ __half g_bh16[(size_t)2 * NBP * DIM];      // fp16 books
__device__ __half g_s16[(size_t)2 * BQ * NBP];        // approx scores (410 MB)
__device__ int    g_cand[2 * BQ * NCAND];             // candidate indices

// ======================= helpers ===========================================
__device__ __forceinline__ uint32_t smem_u32(const void* p) {
    uint32_t a;
    asm("{ .reg .u64 t; cvta.to.shared.u64 t, %1; cvt.u32.u64 %0, t; }" : "=r"(a) : "l"(p));
    return a;
}
__device__ __forceinline__ void ldsm_x4(uint32_t addr, uint32_t* r) {
    asm volatile("ldmatrix.sync.aligned.m8n8.x4.shared.b16 {%0,%1,%2,%3}, [%4];"
        : "=r"(r[0]), "=r"(r[1]), "=r"(r[2]), "=r"(r[3]) : "r"(addr));
}
__device__ __forceinline__ void mma16816(float* d, const uint32_t* a, const uint32_t* b) {
    asm volatile("mma.sync.aligned.m16n8k16.row.col.f32.f16.f16.f32 "
        "{%0,%1,%2,%3}, {%4,%5,%6,%7}, {%8,%9}, {%0,%1,%2,%3};"
        : "+f"(d[0]), "+f"(d[1]), "+f"(d[2]), "+f"(d[3])
        : "r"(a[0]), "r"(a[1]), "r"(a[2]), "r"(a[3]), "r"(b[0]), "r"(b[1]));
}

// ======================= prep kernels ======================================
__global__ void prep_queries(const float* __restrict__ z_rot,
                             const float* __restrict__ z_trans) {
    int warp = (blockIdx.x * blockDim.x + threadIdx.x) >> 5;
    int lane = threadIdx.x & 31;
    if (warp >= BQ) return;

    // p=0: renorm(z_rot)
    float4 v = reinterpret_cast<const float4*>(z_rot + (size_t)warp * DIM)[lane];
    float s = v.x * v.x + v.y * v.y + v.z * v.z + v.w * v.w;
    #pragma unroll
    for (int o = 16; o; o >>= 1) s += __shfl_xor_sync(0xFFFFFFFFu, s, o);
    float inv = 1.0f / sqrtf(s);
    float rv[4] = {v.x * inv, v.y * inv, v.z * inv, v.w * inv};
    size_t base0 = (size_t)warp * DIM + lane * 4;
    #pragma unroll
    for (int j = 0; j < 4; j++) {
        g_qf[base0 + j]   = rv[j];
        g_qh16[base0 + j] = __float2half_rn(rv[j]);
    }

    // p=1: 2*z_trans, plus ||z||^2
    float4 t = reinterpret_cast<const float4*>(z_trans + (size_t)warp * DIM)[lane];
    float sq = t.x * t.x + t.y * t.y + t.z * t.z + t.w * t.w;
    #pragma unroll
    for (int o = 16; o; o >>= 1) sq += __shfl_xor_sync(0xFFFFFFFFu, sq, o);
    float tv[4] = {2.0f * t.x, 2.0f * t.y, 2.0f * t.z, 2.0f * t.w};
    size_t base1 = (size_t)(BQ + warp) * DIM + lane * 4;
    #pragma unroll
    for (int j = 0; j < 4; j++) {
        g_qf[base1 + j]   = tv[j];
        g_qh16[base1 + j] = __float2half_rn(tv[j]);
    }
    if (lane == 0) g_zq[warp] = sq;
}

__global__ void prep_books(const float* __restrict__ z_rot_book,
                           const float* __restrict__ z_trans_book) {
    int warp = (blockIdx.x * blockDim.x + threadIdx.x) >> 5;
    int lane = threadIdx.x & 31;
    if (warp >= NBP) return;

    size_t base0 = (size_t)warp * DIM + lane * 4;
    size_t base1 = (size_t)NBP * DIM + base0;
    if (warp < NB) {
        float4 r = reinterpret_cast<const float4*>(z_rot_book + (size_t)warp * DIM)[lane];
        g_bh16[base0 + 0] = __float2half_rn(r.x);
        g_bh16[base0 + 1] = __float2half_rn(r.y);
        g_bh16[base0 + 2] = __float2half_rn(r.z);
        g_bh16[base0 + 3] = __float2half_rn(r.w);

        float4 t = reinterpret_cast<const float4*>(z_trans_book + (size_t)warp * DIM)[lane];
        float sq = t.x * t.x + t.y * t.y + t.z * t.z + t.w * t.w;
        #pragma unroll
        for (int o = 16; o; o >>= 1) sq += __shfl_xor_sync(0xFFFFFFFFu, sq, o);
        g_bh16[base1 + 0] = __float2half_rn(t.x);
        g_bh16[base1 + 1] = __float2half_rn(t.y);
        g_bh16[base1 + 2] = __float2half_rn(t.z);
        g_bh16[base1 + 3] = __float2half_rn(t.w);
        if (lane == 0) g_bq[warp] = sq;
    } else {
        __half z = __float2half_rn(0.0f);
        #pragma unroll
        for (int j = 0; j < 4; j++) { g_bh16[base0 + j] = z; g_bh16[base1 + j] = z; }
        if (lane == 0) g_bq[warp] = 0.0f;
    }
}

// ======================= single-pass fp16 HMMA GEMM ========================
// CTA: 128 q x 128 n, K=128. One fp16 product pass (approximate scores).
// SMEM: A block + B block, 32KB each, xor-swizzled; 66.5 KB total -> 2 CTA/SM.
#define SMEM_GEMM (2 * 32768 + 1024)

__global__ void __launch_bounds__(512, 2)
score_hmma1() {
    extern __shared__ char smem[];
    const int tid = threadIdx.x;
    const int p     = blockIdx.z;
    const int qbase = blockIdx.y * 128;
    const int nbase = blockIdx.x * 128;

    const __half* srcs[2] = {
        g_qh16 + (size_t)(p * BQ + qbase) * DIM,
        g_bh16 + ((size_t)p * NBP + nbase) * DIM
    };
    #pragma unroll
    for (int b = 0; b < 2; b++) {
        char* dst = smem + b * 32768;
        const __half* src = srcs[b];
        #pragma unroll
        for (int it = 0; it < 4; it++) {
            int idx = it * 512 + tid;        // 0..2047
            int row = idx >> 4;
            int c   = idx & 15;              // 16B chunk
            uint4 v = *reinterpret_cast<const uint4*>(src + (size_t)row * DIM + c * 8);
            *reinterpret_cast<uint4*>(dst + row * 256 + ((c * 16) ^ ((row & 7) << 4))) = v;
        }
    }
    float* zqs = reinterpret_cast<float*>(smem + 65536);
    float* bqs = zqs + 128;
    if (tid < 128)       zqs[tid]       = (p == 1) ? g_zq[qbase + tid]       : 0.0f;
    else if (tid < 256)  bqs[tid - 128] = (p == 1) ? g_bq[nbase + tid - 128] : 0.0f;
    __syncthreads();

    const int lane = tid & 31;
    const int wid  = tid >> 5;
    const int wm = (wid >> 2) * 32;
    const int wn = (wid & 3) * 32;
    const int g  = lane >> 3;
    const int r8 = lane & 7;
    const uint32_t sx = (uint32_t)r8 << 4;
    const int aRowBase  = wm + r8 + ((g & 1) << 3);
    const int aChunkAdd = g >> 1;
    const int bRowBase  = wn + r8 + ((g >> 1) << 3);
    const int bChunkAdd = g & 1;

    uint32_t sb = smem_u32(smem);
    const uint32_t aB = sb;
    const uint32_t bB = sb + 32768u;

    float d[2][4][4];
    #pragma unroll
    for (int f = 0; f < 2; f++)
        #pragma unroll
        for (int j = 0; j < 4; j++)
            #pragma unroll
            for (int e = 0; e < 4; e++) d[f][j][e] = 0.0f;

    #pragma unroll
    for (int s = 0; s < 8; s++) {
        uint32_t a[2][4], b[2][4];
        #pragma unroll
        for (int f = 0; f < 2; f++) {
            int row = aRowBase + f * 16;
            uint32_t ch = (uint32_t)(2 * s + aChunkAdd);
            ldsm_x4(aB + row * 256 + ((ch << 4) ^ sx), a[f]);
        }
        #pragma unroll
        for (int h = 0; h < 2; h++) {
            int row = bRowBase + h * 16;
            uint32_t ch = (uint32_t)(2 * s + bChunkAdd);
            ldsm_x4(bB + row * 256 + ((ch << 4) ^ sx), b[h]);
        }
        #pragma unroll
        for (int f = 0; f < 2; f++)
            #pragma unroll
            for (int j = 0; j < 4; j++)
                mma16816(d[f][j], a[f], &b[j >> 1][(j & 1) * 2]);
    }

    // ---- epilogue: fixups + fp16 store
    __half* S = g_s16 + ((size_t)p * BQ + qbase) * NBP + nbase;
    #pragma unroll
    for (int f = 0; f < 2; f++) {
        int mA = wm + f * 16 + (lane >> 2);
        int mB = mA + 8;
        float zqA = zqs[mA], zqB = zqs[mB];
        #pragma unroll
        for (int j = 0; j < 4; j++) {
            int n = wn + j * 8 + (lane & 3) * 2;
            float b0 = bqs[n], b1 = bqs[n + 1];
            __half2 h0 = __floats2half2_rn(d[f][j][0] - zqA - b0, d[f][j][1] - zqA - b1);
            __half2 h1 = __floats2half2_rn(d[f][j][2] - zqB - b0, d[f][j][3] - zqB - b1);
            *reinterpret_cast<__half2*>(S + (size_t)mA * NBP + n) = h0;
            *reinterpret_cast<__half2*>(S + (size_t)mB * NBP + n) = h1;
        }
    }
}

// ======================= candidate selection (approx top-32) ===============
#define LSLOT 8
__global__ void __launch_bounds__(256)
cand_kernel() {
    const int p   = blockIdx.x >> 11;
    const int r   = blockIdx.x & 2047;
    const int tid = threadIdx.x;
    const __half* s = g_s16 + ((size_t)p * BQ + r) * NBP;

    float lv[LSLOT];
    int   li[LSLOT];
    #pragma unroll
    for (int t = 0; t < LSLOT; t++) { lv[t] = -FLT_MAX; li[t] = 0x7FFFFFFF; }
    float vmin = -FLT_MAX; int minidx = 0x7FFFFFFF; int minslot = 0;

    for (int n = tid; n < NB; n += 256) {
        float v = __half2float(s[n]);
        if (v > vmin || (v == vmin && n < minidx)) {
            #pragma unroll
            for (int t = 0; t < LSLOT; t++)
                if (t == minslot) { lv[t] = v; li[t] = n; }
            vmin = lv[0]; minidx = li[0]; minslot = 0;
            #pragma unroll
            for (int t = 1; t < LSLOT; t++)
                if (lv[t] < vmin || (lv[t] == vmin && li[t] > minidx)) {
                    vmin = lv[t]; minidx = li[t]; minslot = t;
                }
        }
    }

    __shared__ float sv[256 * LSLOT];
    __shared__ int   si[256 * LSLOT];
    __shared__ float wv[8];
    __shared__ int   wi[8], wp[8];

    #pragma unroll
    for (int t = 0; t < LSLOT; t++) {
        sv[tid * LSLOT + t] = lv[t];
        si[tid * LSLOT + t] = li[t];
    }
    __syncthreads();

    int* cand = g_cand + ((size_t)p * BQ + r) * NCAND;

    for (int k = 0; k < NCAND; k++) {
        float bv = -FLT_MAX; int bi = 0x7FFFFFFF; int bp = 0;
        #pragma unroll
        for (int e = 0; e < LSLOT; e++) {
            int pos = tid + e * 256;
            float v = sv[pos]; int ii = si[pos];
            if (v > bv || (v == bv && ii < bi)) { bv = v; bi = ii; bp = pos; }
        }
        #pragma unroll
        for (int o = 16; o; o >>= 1) {
            float ov = __shfl_down_sync(0xFFFFFFFFu, bv, o);
            int   oi = __shfl_down_sync(0xFFFFFFFFu, bi, o);
            int   op = __shfl_down_sync(0xFFFFFFFFu, bp, o);
            if (ov > bv || (ov == bv && oi < bi)) { bv = ov; bi = oi; bp = op; }
        }
        if ((tid & 31) == 0) { int w = tid >> 5; wv[w] = bv; wi[w] = bi; wp[w] = bp; }
        __syncthreads();
        if (tid == 0) {
            float gv = wv[0]; int gi = wi[0]; int gp = wp[0];
            #pragma unroll
            for (int w = 1; w < 8; w++)
                if (wv[w] > gv || (wv[w] == gv && wi[w] < gi)) { gv = wv[w]; gi = wi[w]; gp = wp[w]; }
            sv[gp] = -FLT_MAX; si[gp] = 0x7FFFFFFF;
            cand[k] = gi;
        }
        __syncthreads();
    }
}

// ======================= exact refine + final top-20 =======================
__global__ void __launch_bounds__(128)
refine_kernel(const float* __restrict__ z_rot_book,
              const float* __restrict__ z_trans_book,
              const float* __restrict__ rot_book,
              const float* __restrict__ trans_book,
              float* __restrict__ out) {
    const int p = blockIdx.y;
    const int r = blockIdx.x;
    const int tid  = threadIdx.x;
    const int wid  = tid >> 5;
    const int lane = tid & 31;

    __shared__ float sval[NCAND];
    __shared__ int   sidx[NCAND];

    // staged A row (fp32): p0 = renormed z_rot, p1 = 2*z_trans
    float4 a = reinterpret_cast<const float4*>(g_qf + (size_t)(p * BQ + r) * DIM)[lane];
    const float zq = (p == 1) ? g_zq[r] : 0.0f;
    const float* Bsrc = (p == 0) ? z_rot_book : z_trans_book;
    const int* cand = g_cand + ((size_t)p * BQ + r) * NCAND;

    #pragma unroll
    for (int t = 0; t < NCAND / 4; t++) {         // 8 candidates per warp
        int ci = cand[wid * (NCAND / 4) + t];
        float4 b = reinterpret_cast<const float4*>(Bsrc + (size_t)ci * DIM)[lane];
        float sdot = a.x * b.x + a.y * b.y + a.z * b.z + a.w * b.w;
        #pragma unroll
        for (int o = 16; o; o >>= 1) sdot += __shfl_xor_sync(0xFFFFFFFFu, sdot, o);
        if (lane == 0) {
            float sc = sdot - zq - ((p == 1) ? g_bq[ci] : 0.0f);
            sval[wid * (NCAND / 4) + t] = sc;
            sidx[wid * (NCAND / 4) + t] = ci;
        }
    }
    __syncthreads();

    if (wid == 0) {
        float v = sval[lane];
        int  ix = sidx[lane];
        const size_t BK = (size_t)BQ * TOPK;

        #pragma unroll
        for (int k = 0; k < TOPK; k++) {
            float bv = v; int bi = ix; int bl = lane;
            #pragma unroll
            for (int o = 16; o; o >>= 1) {
                float ov = __shfl_xor_sync(0xFFFFFFFFu, bv, o);
                int   oi = __shfl_xor_sync(0xFFFFFFFFu, bi, o);
                int   ol = __shfl_xor_sync(0xFFFFFFFFu, bl, o);
                if (ov > bv || (ov == bv && oi < bi)) { bv = ov; bi = oi; bl = ol; }
            }
            if (lane == bl) { v = -FLT_MAX; ix = 0x7FFFFFFF; }
            if (lane == 0) {
                size_t rk = (size_t)r * TOPK + k;
                if (p == 0) {
                    out[rk]          = bv;
                    out[BK + rk]     = (float)bi;
                    out[2 * BK + rk] = rot_book[bi];
                } else {
                    out[3 * BK + rk] = bv;
                    out[4 * BK + rk] = (float)bi;
                    out[5 * BK + rk * 3 + 0] = trans_book[(size_t)bi * 3 + 0];
                    out[5 * BK + rk * 3 + 1] = trans_book[(size_t)bi * 3 + 1];
                    out[5 * BK + rk * 3 + 2] = trans_book[(size_t)bi * 3 + 2];
                }
            }
        }
    }
}

// ======================= launch ============================================
extern "C" void kernel_launch(void* const* d_in, const int* in_sizes, int n_in,
                              void* d_out, int out_size) {
    const float* z_rot        = (const float*)d_in[0];
    const float* z_trans      = (const float*)d_in[1];
    const float* z_rot_book   = (const float*)d_in[2];
    const float* z_trans_book = (const float*)d_in[3];
    const float* rot_book     = (const float*)d_in[4];
    const float* trans_book   = (const float*)d_in[5];
    float* out = (float*)d_out;

    prep_queries<<<BQ / 8, 256>>>(z_rot, z_trans);
    prep_books<<<(NBP + 7) / 8, 256>>>(z_rot_book, z_trans_book);

    cudaFuncSetAttribute(score_hmma1, cudaFuncAttributeMaxDynamicSharedMemorySize, SMEM_GEMM);
    dim3 grid(NBP / 128, BQ / 128, 2);
    score_hmma1<<<grid, 512, SMEM_GEMM>>>();

    cand_kernel<<<2 * BQ, 256>>>();

    dim3 rgrid(BQ, 2);
    refine_kernel<<<rgrid, 128>>>(z_rot_book, z_trans_book, rot_book, trans_book, out);
}

// round 7
// speedup vs baseline: 6.9577x; 1.9989x over previous
#include <cuda_runtime.h>
#include <cuda_fp16.h>
#include <cfloat>
#include <cstdint>

// Problem constants
#define BQ    2048
#define NB    50000
#define NBP   50048     // 391*128
#define DIM   128
#define TOPK  20
#define NCAND 32
#define NCHUNK 6250     // 50000 / 8
#define BUFCAP 4096
#define COMPRESS_AT 2048

// ======================= device scratch ====================================
__device__ float  g_zq[BQ];
__device__ float  g_bq[NBP];
__device__ float  g_qf[2 * BQ * DIM];
__device__ __half g_qh16[2 * BQ * DIM];
__device__ __half g_bh16[(size_t)2 * NBP * DIM];
__device__ uint4  g_s16v[(size_t)2 * BQ * NBP / 8];   // approx scores as fp16, uint4-aligned
__device__ int    g_cand[2 * BQ * NCAND];

// ======================= helpers ===========================================
__device__ __forceinline__ uint32_t smem_u32(const void* p) {
    uint32_t a;
    asm("{ .reg .u64 t; cvta.to.shared.u64 t, %1; cvt.u32.u64 %0, t; }" : "=r"(a) : "l"(p));
    return a;
}
__device__ __forceinline__ void ldsm_x4(uint32_t addr, uint32_t* r) {
    asm volatile("ldmatrix.sync.aligned.m8n8.x4.shared.b16 {%0,%1,%2,%3}, [%4];"
        : "=r"(r[0]), "=r"(r[1]), "=r"(r[2]), "=r"(r[3]) : "r"(addr));
}
__device__ __forceinline__ void mma16816(float* d, const uint32_t* a, const uint32_t* b) {
    asm volatile("mma.sync.aligned.m16n8k16.row.col.f32.f16.f16.f32 "
        "{%0,%1,%2,%3}, {%4,%5,%6,%7}, {%8,%9}, {%0,%1,%2,%3};"
        : "+f"(d[0]), "+f"(d[1]), "+f"(d[2]), "+f"(d[3])
        : "r"(a[0]), "r"(a[1]), "r"(a[2]), "r"(a[3]), "r"(b[0]), "r"(b[1]));
}

// order-preserving transform: half bits (16) -> uint16 with integer order
__device__ __forceinline__ unsigned int h2ord(unsigned int u) {
    return u ^ (0x8000u | (0x7FFFu & (0u - (u >> 15))));
}
// inverse: ord16 -> half bits
__device__ __forceinline__ unsigned int ord2h(unsigned int o) {
    return (o & 0x8000u) ? (o ^ 0x8000u) : ((o ^ 0xFFFFu) & 0xFFFFu);
}
__device__ __forceinline__ __half chunk_max8(uint4 v) {
    __half2 a = __hmax2(*reinterpret_cast<__half2*>(&v.x), *reinterpret_cast<__half2*>(&v.y));
    __half2 b = __hmax2(*reinterpret_cast<__half2*>(&v.z), *reinterpret_cast<__half2*>(&v.w));
    __half2 m = __hmax2(a, b);
    return __hmax(__low2half(m), __high2half(m));
}

// ======================= prep kernels ======================================
__global__ void prep_queries(const float* __restrict__ z_rot,
                             const float* __restrict__ z_trans) {
    int warp = (blockIdx.x * blockDim.x + threadIdx.x) >> 5;
    int lane = threadIdx.x & 31;
    if (warp >= BQ) return;

    float4 v = reinterpret_cast<const float4*>(z_rot + (size_t)warp * DIM)[lane];
    float s = v.x * v.x + v.y * v.y + v.z * v.z + v.w * v.w;
    #pragma unroll
    for (int o = 16; o; o >>= 1) s += __shfl_xor_sync(0xFFFFFFFFu, s, o);
    float inv = 1.0f / sqrtf(s);
    float rv[4] = {v.x * inv, v.y * inv, v.z * inv, v.w * inv};
    size_t base0 = (size_t)warp * DIM + lane * 4;
    #pragma unroll
    for (int j = 0; j < 4; j++) {
        g_qf[base0 + j]   = rv[j];
        g_qh16[base0 + j] = __float2half_rn(rv[j]);
    }

    float4 t = reinterpret_cast<const float4*>(z_trans + (size_t)warp * DIM)[lane];
    float sq = t.x * t.x + t.y * t.y + t.z * t.z + t.w * t.w;
    #pragma unroll
    for (int o = 16; o; o >>= 1) sq += __shfl_xor_sync(0xFFFFFFFFu, sq, o);
    float tv[4] = {2.0f * t.x, 2.0f * t.y, 2.0f * t.z, 2.0f * t.w};
    size_t base1 = (size_t)(BQ + warp) * DIM + lane * 4;
    #pragma unroll
    for (int j = 0; j < 4; j++) {
        g_qf[base1 + j]   = tv[j];
        g_qh16[base1 + j] = __float2half_rn(tv[j]);
    }
    if (lane == 0) g_zq[warp] = sq;
}

__global__ void prep_books(const float* __restrict__ z_rot_book,
                           const float* __restrict__ z_trans_book) {
    int warp = (blockIdx.x * blockDim.x + threadIdx.x) >> 5;
    int lane = threadIdx.x & 31;
    if (warp >= NBP) return;

    size_t base0 = (size_t)warp * DIM + lane * 4;
    size_t base1 = (size_t)NBP * DIM + base0;
    if (warp < NB) {
        float4 r = reinterpret_cast<const float4*>(z_rot_book + (size_t)warp * DIM)[lane];
        g_bh16[base0 + 0] = __float2half_rn(r.x);
        g_bh16[base0 + 1] = __float2half_rn(r.y);
        g_bh16[base0 + 2] = __float2half_rn(r.z);
        g_bh16[base0 + 3] = __float2half_rn(r.w);

        float4 t = reinterpret_cast<const float4*>(z_trans_book + (size_t)warp * DIM)[lane];
        float sq = t.x * t.x + t.y * t.y + t.z * t.z + t.w * t.w;
        #pragma unroll
        for (int o = 16; o; o >>= 1) sq += __shfl_xor_sync(0xFFFFFFFFu, sq, o);
        g_bh16[base1 + 0] = __float2half_rn(t.x);
        g_bh16[base1 + 1] = __float2half_rn(t.y);
        g_bh16[base1 + 2] = __float2half_rn(t.z);
        g_bh16[base1 + 3] = __float2half_rn(t.w);
        if (lane == 0) g_bq[warp] = sq;
    } else {
        __half z = __float2half_rn(0.0f);
        #pragma unroll
        for (int j = 0; j < 4; j++) { g_bh16[base0 + j] = z; g_bh16[base1 + j] = z; }
        if (lane == 0) g_bq[warp] = 0.0f;
    }
}

// ======================= single-pass fp16 HMMA GEMM ========================
#define SMEM_GEMM (2 * 32768 + 1024)

__global__ void __launch_bounds__(512, 2)
score_hmma1() {
    extern __shared__ char smem[];
    const int tid = threadIdx.x;
    const int p     = blockIdx.z;
    const int qbase = blockIdx.y * 128;
    const int nbase = blockIdx.x * 128;

    const __half* srcs[2] = {
        g_qh16 + (size_t)(p * BQ + qbase) * DIM,
        g_bh16 + ((size_t)p * NBP + nbase) * DIM
    };
    #pragma unroll
    for (int b = 0; b < 2; b++) {
        char* dst = smem + b * 32768;
        const __half* src = srcs[b];
        #pragma unroll
        for (int it = 0; it < 4; it++) {
            int idx = it * 512 + tid;
            int row = idx >> 4;
            int c   = idx & 15;
            uint4 v = *reinterpret_cast<const uint4*>(src + (size_t)row * DIM + c * 8);
            *reinterpret_cast<uint4*>(dst + row * 256 + ((c * 16) ^ ((row & 7) << 4))) = v;
        }
    }
    float* zqs = reinterpret_cast<float*>(smem + 65536);
    float* bqs = zqs + 128;
    if (tid < 128)       zqs[tid]       = (p == 1) ? g_zq[qbase + tid]       : 0.0f;
    else if (tid < 256)  bqs[tid - 128] = (p == 1) ? g_bq[nbase + tid - 128] : 0.0f;
    __syncthreads();

    const int lane = tid & 31;
    const int wid  = tid >> 5;
    const int wm = (wid >> 2) * 32;
    const int wn = (wid & 3) * 32;
    const int g  = lane >> 3;
    const int r8 = lane & 7;
    const uint32_t sx = (uint32_t)r8 << 4;
    const int aRowBase  = wm + r8 + ((g & 1) << 3);
    const int aChunkAdd = g >> 1;
    const int bRowBase  = wn + r8 + ((g >> 1) << 3);
    const int bChunkAdd = g & 1;

    uint32_t sb = smem_u32(smem);
    const uint32_t aB = sb;
    const uint32_t bB = sb + 32768u;

    float d[2][4][4];
    #pragma unroll
    for (int f = 0; f < 2; f++)
        #pragma unroll
        for (int j = 0; j < 4; j++)
            #pragma unroll
            for (int e = 0; e < 4; e++) d[f][j][e] = 0.0f;

    #pragma unroll
    for (int s = 0; s < 8; s++) {
        uint32_t a[2][4], b[2][4];
        #pragma unroll
        for (int f = 0; f < 2; f++) {
            int row = aRowBase + f * 16;
            uint32_t ch = (uint32_t)(2 * s + aChunkAdd);
            ldsm_x4(aB + row * 256 + ((ch << 4) ^ sx), a[f]);
        }
        #pragma unroll
        for (int h = 0; h < 2; h++) {
            int row = bRowBase + h * 16;
            uint32_t ch = (uint32_t)(2 * s + bChunkAdd);
            ldsm_x4(bB + row * 256 + ((ch << 4) ^ sx), b[h]);
        }
        #pragma unroll
        for (int f = 0; f < 2; f++)
            #pragma unroll
            for (int j = 0; j < 4; j++)
                mma16816(d[f][j], a[f], &b[j >> 1][(j & 1) * 2]);
    }

    __half* S = reinterpret_cast<__half*>(g_s16v) + ((size_t)p * BQ + qbase) * NBP + nbase;
    #pragma unroll
    for (int f = 0; f < 2; f++) {
        int mA = wm + f * 16 + (lane >> 2);
        int mB = mA + 8;
        float zqA = zqs[mA], zqB = zqs[mB];
        #pragma unroll
        for (int j = 0; j < 4; j++) {
            int n = wn + j * 8 + (lane & 3) * 2;
            float b0 = bqs[n], b1 = bqs[n + 1];
            __half2 h0 = __floats2half2_rn(d[f][j][0] - zqA - b0, d[f][j][1] - zqA - b1);
            __half2 h1 = __floats2half2_rn(d[f][j][2] - zqB - b0, d[f][j][3] - zqB - b1);
            *reinterpret_cast<__half2*>(S + (size_t)mA * NBP + n) = h0;
            *reinterpret_cast<__half2*>(S + (size_t)mB * NBP + n) = h1;
        }
    }
}

// ======================= candidate selection ===============================
// Per row: threshold-filtered scan with packed uint32 keys.
__device__ __forceinline__ void append_chunk(uint4 v, int n0, unsigned int T,
                                             int* cnt, unsigned int* keybuf,
                                             unsigned int skipkey) {
    unsigned int w[4] = {v.x, v.y, v.z, v.w};
    #pragma unroll
    for (int e = 0; e < 4; e++) {
        unsigned int lo = w[e] & 0xFFFFu;
        unsigned int hi = w[e] >> 16;
        unsigned int k0 = (h2ord(lo) << 16) | (0xFFFFu - (unsigned int)(n0 + 2 * e));
        unsigned int k1 = (h2ord(hi) << 16) | (0xFFFFu - (unsigned int)(n0 + 2 * e + 1));
        if (k0 > T && k0 != skipkey) {
            int pp = atomicAdd(cnt, 1);
            if (pp < BUFCAP) keybuf[pp] = k0;
        }
        if (k1 > T && k1 != skipkey) {
            int pp = atomicAdd(cnt, 1);
            if (pp < BUFCAP) keybuf[pp] = k1;
        }
    }
}

// warp-0 only: extract top-32 keys from keybuf[0..m) into top32, zeroing winners
__device__ __forceinline__ void extract32(unsigned int* keybuf, unsigned int* top32,
                                          int m, int lane) {
    #pragma unroll 1
    for (int k = 0; k < 32; k++) {
        unsigned int best = 0; int bpos = -1;
        for (int i = lane; i < m; i += 32) {
            unsigned int kk = keybuf[i];
            if (kk > best) { best = kk; bpos = i; }
        }
        #pragma unroll
        for (int o = 16; o; o >>= 1) {
            unsigned int ob = __shfl_down_sync(0xFFFFFFFFu, best, o);
            int          op = __shfl_down_sync(0xFFFFFFFFu, bpos, o);
            if (ob > best) { best = ob; bpos = op; }
        }
        if (lane == 0) {
            top32[k] = best;
            if (bpos >= 0) keybuf[bpos] = 0;
        }
        __syncwarp();
    }
}

__global__ void __launch_bounds__(256)
cand_kernel() {
    const int p   = blockIdx.x >> 11;
    const int r   = blockIdx.x & 2047;
    const int tid = threadIdx.x;
    const int lane = tid & 31;
    const int wid  = tid >> 5;
    const uint4* row = g_s16v + (size_t)((size_t)p * BQ + r) * (NBP / 8);

    __shared__ unsigned int keybuf[BUFCAP];
    __shared__ unsigned int top32[32];
    __shared__ int s_cnt;
    __shared__ unsigned int s_T;    // packed-key threshold
    __shared__ unsigned int s_Th;   // half bits of threshold value

    // ---- seed: chunk 0 (first 2048 elements), per-thread chunk-max key
    uint4 v0 = row[tid];
    unsigned int mybest = 0;
    {
        unsigned int w[4] = {v0.x, v0.y, v0.z, v0.w};
        #pragma unroll
        for (int e = 0; e < 4; e++) {
            unsigned int lo = w[e] & 0xFFFFu;
            unsigned int hi = w[e] >> 16;
            unsigned int k0 = (h2ord(lo) << 16) | (0xFFFFu - (unsigned int)(tid * 8 + 2 * e));
            unsigned int k1 = (h2ord(hi) << 16) | (0xFFFFu - (unsigned int)(tid * 8 + 2 * e + 1));
            if (k0 > mybest) mybest = k0;
            if (k1 > mybest) mybest = k1;
        }
    }
    keybuf[tid] = mybest;
    __syncthreads();
    if (wid == 0) extract32(keybuf, top32, 256, lane);
    __syncthreads();
    if (tid < 32) keybuf[tid] = top32[tid];
    if (tid == 0) {
        s_cnt = 32;
        s_T   = top32[31];
        s_Th  = ord2h(top32[31] >> 16);
    }
    __syncthreads();

    // ---- re-scan chunk 0 vs T (skip own max: already in buffer if it survived)
    append_chunk(v0, tid * 8, s_T, &s_cnt, keybuf, mybest);
    __syncthreads();

    // ---- main scan
    #pragma unroll 1
    for (int it = 1; it < 25; ++it) {
        unsigned int Tv = s_T;
        __half Th = __ushort_as_half((unsigned short)s_Th);
        int c = it * 256 + tid;
        if (c < NCHUNK) {
            uint4 v = row[c];
            if (__hge(chunk_max8(v), Th))
                append_chunk(v, c * 8, Tv, &s_cnt, keybuf, 0u);
        }
        __syncthreads();
        if (s_cnt >= COMPRESS_AT) {     // uniform branch; correctness net (rare)
            int m = min(s_cnt, BUFCAP);
            if (wid == 0) extract32(keybuf, top32, m, lane);
            __syncthreads();
            if (tid < 32) keybuf[tid] = top32[tid];
            if (tid == 0) {
                s_cnt = 32;
                s_T   = top32[31];
                s_Th  = ord2h(top32[31] >> 16);
            }
            __syncthreads();
        }
    }

    // ---- final: top-32 set of buffer -> candidate indices
    int m = min(s_cnt, BUFCAP);
    if (wid == 0) extract32(keybuf, top32, m, lane);
    __syncthreads();
    if (tid < 32) {
        unsigned int key = top32[tid];
        int idx = (int)(0xFFFFu - (key & 0xFFFFu));
        g_cand[((size_t)p * BQ + r) * NCAND + tid] = idx;
    }
}

// ======================= exact refine + final top-20 =======================
__global__ void __launch_bounds__(128)
refine_kernel(const float* __restrict__ z_rot_book,
              const float* __restrict__ z_trans_book,
              const float* __restrict__ rot_book,
              const float* __restrict__ trans_book,
              float* __restrict__ out) {
    const int p = blockIdx.y;
    const int r = blockIdx.x;
    const int tid  = threadIdx.x;
    const int wid  = tid >> 5;
    const int lane = tid & 31;

    __shared__ float sval[NCAND];
    __shared__ int   sidx[NCAND];

    float4 a = reinterpret_cast<const float4*>(g_qf + (size_t)(p * BQ + r) * DIM)[lane];
    const float zq = (p == 1) ? g_zq[r] : 0.0f;
    const float* Bsrc = (p == 0) ? z_rot_book : z_trans_book;
    const int* cand = g_cand + ((size_t)p * BQ + r) * NCAND;

    #pragma unroll
    for (int t = 0; t < NCAND / 4; t++) {
        int ci = cand[wid * (NCAND / 4) + t];
        float4 b = reinterpret_cast<const float4*>(Bsrc + (size_t)ci * DIM)[lane];
        float sdot = a.x * b.x + a.y * b.y + a.z * b.z + a.w * b.w;
        #pragma unroll
        for (int o = 16; o; o >>= 1) sdot += __shfl_xor_sync(0xFFFFFFFFu, sdot, o);
        if (lane == 0) {
            float sc = sdot - zq - ((p == 1) ? g_bq[ci] : 0.0f);
            sval[wid * (NCAND / 4) + t] = sc;
            sidx[wid * (NCAND / 4) + t] = ci;
        }
    }
    __syncthreads();

    if (wid == 0) {
        float v = sval[lane];
        int  ix = sidx[lane];
        const size_t BK = (size_t)BQ * TOPK;

        #pragma unroll
        for (int k = 0; k < TOPK; k++) {
            float bv = v; int bi = ix; int bl = lane;
            #pragma unroll
            for (int o = 16; o; o >>= 1) {
                float ov = __shfl_xor_sync(0xFFFFFFFFu, bv, o);
                int   oi = __shfl_xor_sync(0xFFFFFFFFu, bi, o);
                int   ol = __shfl_xor_sync(0xFFFFFFFFu, bl, o);
                if (ov > bv || (ov == bv && oi < bi)) { bv = ov; bi = oi; bl = ol; }
            }
            if (lane == bl) { v = -FLT_MAX; ix = 0x7FFFFFFF; }
            if (lane == 0) {
                size_t rk = (size_t)r * TOPK + k;
                if (p == 0) {
                    out[rk]          = bv;
                    out[BK + rk]     = (float)bi;
                    out[2 * BK + rk] = rot_book[bi];
                } else {
                    out[3 * BK + rk] = bv;
                    out[4 * BK + rk] = (float)bi;
                    out[5 * BK + rk * 3 + 0] = trans_book[(size_t)bi * 3 + 0];
                    out[5 * BK + rk * 3 + 1] = trans_book[(size_t)bi * 3 + 1];
                    out[5 * BK + rk * 3 + 2] = trans_book[(size_t)bi * 3 + 2];
                }
            }
        }
    }
}

// ======================= launch ============================================
extern "C" void kernel_launch(void* const* d_in, const int* in_sizes, int n_in,
                              void* d_out, int out_size) {
    const float* z_rot        = (const float*)d_in[0];
    const float* z_trans      = (const float*)d_in[1];
    const float* z_rot_book   = (const float*)d_in[2];
    const float* z_trans_book = (const float*)d_in[3];
    const float* rot_book     = (const float*)d_in[4];
    const float* trans_book   = (const float*)d_in[5];
    float* out = (float*)d_out;

    prep_queries<<<BQ / 8, 256>>>(z_rot, z_trans);
    prep_books<<<(NBP + 7) / 8, 256>>>(z_rot_book, z_trans_book);

    cudaFuncSetAttribute(score_hmma1, cudaFuncAttributeMaxDynamicSharedMemorySize, SMEM_GEMM);
    dim3 grid(NBP / 128, BQ / 128, 2);
    score_hmma1<<<grid, 512, SMEM_GEMM>>>();

    cand_kernel<<<2 * BQ, 256>>>();

    dim3 rgrid(BQ, 2);
    refine_kernel<<<rgrid, 128>>>(z_rot_book, z_trans_book, rot_book, trans_book, out);
}